// round 16
// baseline (speedup 1.0000x reference)
#include <cuda_runtime.h>
#include <cuda_fp16.h>
#include <stdint.h>
#include <math_constants.h>

#define BB 4
#define TT 2048
#define DD 1024
#define KCH 64

// ---- scratch (allocation-free rule: __device__ globals) ----
__device__ __align__(256) __half g_x16[(size_t)BB * TT * DD];
__device__ __align__(256) __half g_w16[3 * (size_t)DD * DD];     // Wq,Wk,Wv
__device__ __align__(256) __half g_q16[(size_t)BB * TT * DD];
__device__ __align__(256) __half g_k16[(size_t)BB * TT * DD];
__device__ __align__(256) __half g_v16[(size_t)BB * TT * DD];
__device__ __align__(256) __half g_p16[(size_t)BB * TT * TT];    // unnormalized exp(s), fp16
__device__ __align__(256) float  g_rsum[(size_t)BB * TT];        // per-row sum of exp(s)
__device__ int g_cnt[256];   // [0..127] Q/K rowblocks, [128..191] scores rowblocks, [192..195] V per batch

// SMEM: 3 stages x (A 16K | B 16K)
#define STAGE 32768
#define NSTAGE 3
#define SMEM_BYTES (NSTAGE * STAGE)   // 98304

__device__ __forceinline__ uint32_t smem_u32(const void* p) {
    uint32_t a;
    asm("{ .reg .u64 t; cvta.to.shared.u64 t, %1; cvt.u32.u64 %0, t; }" : "=r"(a) : "l"(p));
    return a;
}
__device__ __forceinline__ void cpa16(uint32_t dst, const void* src) {
    asm volatile("cp.async.cg.shared.global [%0], [%1], 16;" :: "r"(dst), "l"(src));
}
__device__ __forceinline__ void cpa_commit() { asm volatile("cp.async.commit_group;" ::: "memory"); }
__device__ __forceinline__ void cpa_wait1()  { asm volatile("cp.async.wait_group 1;" ::: "memory"); }

__device__ __forceinline__ void ldsm4(uint32_t addr, uint32_t r[4]) {
    asm volatile("ldmatrix.sync.aligned.m8n8.x4.shared.b16 {%0,%1,%2,%3}, [%4];"
                 : "=r"(r[0]), "=r"(r[1]), "=r"(r[2]), "=r"(r[3]) : "r"(addr));
}
__device__ __forceinline__ void ldsm4t(uint32_t addr, uint32_t r[4]) {
    asm volatile("ldmatrix.sync.aligned.m8n8.x4.trans.shared.b16 {%0,%1,%2,%3}, [%4];"
                 : "=r"(r[0]), "=r"(r[1]), "=r"(r[2]), "=r"(r[3]) : "r"(addr));
}
__device__ __forceinline__ void mma_f16(float c[4], const uint32_t a[4],
                                        uint32_t b0, uint32_t b1) {
    asm volatile("mma.sync.aligned.m16n8k16.row.col.f32.f16.f16.f32 "
                 "{%0,%1,%2,%3}, {%4,%5,%6,%7}, {%8,%9}, {%0,%1,%2,%3};"
                 : "+f"(c[0]), "+f"(c[1]), "+f"(c[2]), "+f"(c[3])
                 : "r"(a[0]), "r"(a[1]), "r"(a[2]), "r"(a[3]), "r"(b0), "r"(b1));
}

// producer/consumer flags (block-id monotone order guarantees progress)
__device__ __forceinline__ void signal_cnt(int* c) {
    __threadfence();
    __syncthreads();
    if (threadIdx.x == 0) atomicAdd(c, 1);
}
__device__ __forceinline__ void wait_cnt(const int* c, int target) {
    if (threadIdx.x == 0) {
        int v;
        do {
            asm volatile("ld.global.acquire.gpu.b32 %0, [%1];" : "=r"(v) : "l"(c));
        } while (v < target);
    }
    __syncthreads();
}

// Epilogue modes
#define EPI_F16   0
#define EPI_EXP   1
#define EPI_NORM  2

// ---------------------------------------------------------------------------
// 1-pass fp16 HMMA GEMM (R11/R13 core): C[m,n] = sum_k A[m,k]*B'[k,n]
// ---------------------------------------------------------------------------
template <bool BT, int EPI>
__device__ __forceinline__ void gemm_f16(const __half* __restrict__ A,
                                         const __half* __restrict__ Bm,
                                         float* Cf, __half* Ch,
                                         float* rsum,
                                         int Ntot, int K, float scale,
                                         int m0, int n0)
{
    extern __shared__ char smc[];
    const uint32_t sb  = smem_u32(smc);
    const int tid  = threadIdx.x;
    const int lane = tid & 31;
    const int wid  = tid >> 5;
    const int wr   = wid >> 1;
    const int wc   = wid & 1;

    float acc[4][8][4];
#pragma unroll
    for (int i = 0; i < 4; i++)
#pragma unroll
        for (int j = 0; j < 8; j++)
#pragma unroll
            for (int e = 0; e < 4; e++) acc[i][j][e] = 0.f;

    const int nch = K / KCH;

    auto stage = [&](int c, int s) {
        const uint32_t base = sb + s * STAGE;
        const int k0 = c * KCH;
#pragma unroll
        for (int i = 0; i < 8; i++) {
            int u = tid + i * 128;
            int row = u >> 3, ch = u & 7;
            uint32_t off = (uint32_t)(row * 128 + ((ch * 16) ^ ((row & 7) * 16)));
            cpa16(base + off, A + (size_t)(m0 + row) * K + k0 + ch * 8);
        }
        if (BT) {
#pragma unroll
            for (int i = 0; i < 8; i++) {
                int u = tid + i * 128;
                int row = u >> 3, ch = u & 7;
                uint32_t off = (uint32_t)(row * 128 + ((ch * 16) ^ ((row & 7) * 16)));
                cpa16(base + 16384 + off, Bm + (size_t)(n0 + row) * K + k0 + ch * 8);
            }
        } else {
#pragma unroll
            for (int i = 0; i < 8; i++) {
                int u = tid + i * 128;
                int kr = u >> 4, ch = u & 15;
                uint32_t off = (uint32_t)(kr * 256 + ((ch * 16) ^ ((kr & 7) * 16)));
                cpa16(base + 16384 + off, Bm + (size_t)(k0 + kr) * Ntot + n0 + ch * 8);
            }
        }
        cpa_commit();
    };

    auto load_a = [&](uint32_t base, int ks, uint32_t Af[4][4]) {
        const int arow = lane & 15;
        const uint32_t ach = (uint32_t)(((ks * 2 + (lane >> 4)) * 16) ^ ((lane & 7) * 16));
#pragma unroll
        for (int mt = 0; mt < 4; mt++) {
            const uint32_t aoff = (uint32_t)((wr * 64 + mt * 16 + arow) * 128) + ach;
            ldsm4(base + aoff, Af[mt]);
        }
    };
    auto load_b = [&](uint32_t base, int ks, uint32_t Bf[4][4]) {
        if (BT) {
            const int brow = (lane >> 4) * 8 + (lane & 7);
            const uint32_t bch =
                (uint32_t)(((ks * 2 + ((lane >> 3) & 1)) * 16) ^ ((lane & 7) * 16));
#pragma unroll
            for (int ng = 0; ng < 4; ng++) {
                const uint32_t boff = (uint32_t)((wc * 64 + ng * 16 + brow) * 128) + bch;
                ldsm4(base + 16384 + boff, Bf[ng]);
            }
        } else {
            const int krow = ks * 16 + (lane & 15);
#pragma unroll
            for (int ng = 0; ng < 4; ng++) {
                const uint32_t chunk =
                    (uint32_t)(wc * 8 + ng * 2 + (lane >> 4)) ^ (uint32_t)(lane & 7);
                ldsm4t(base + 16384 + (uint32_t)(krow * 256) + chunk * 16, Bf[ng]);
            }
        }
    };

    auto compute = [&](int s) {
        const uint32_t base = sb + s * STAGE;
        uint32_t Af[2][4][4], Bf[2][4][4];
        load_a(base, 0, Af[0]);
        load_b(base, 0, Bf[0]);
#pragma unroll
        for (int ks = 0; ks < KCH / 16; ks++) {
            const int cur = ks & 1;
            if (ks + 1 < KCH / 16) {
                load_a(base, ks + 1, Af[cur ^ 1]);
                load_b(base, ks + 1, Bf[cur ^ 1]);
            }
#pragma unroll
            for (int mt = 0; mt < 4; mt++)
#pragma unroll
                for (int ng = 0; ng < 4; ng++) {
                    mma_f16(acc[mt][ng * 2],     Af[cur][mt], Bf[cur][ng][0], Bf[cur][ng][1]);
                    mma_f16(acc[mt][ng * 2 + 1], Af[cur][mt], Bf[cur][ng][2], Bf[cur][ng][3]);
                }
        }
    };

    stage(0, 0);
    if (nch > 1) stage(1, 1);
    for (int c = 0; c < nch; c++) {
        cpa_wait1();
        __syncthreads();
        if (c + 2 < nch) stage(c + 2, (c + 2) % NSTAGE);
        compute(c % NSTAGE);
    }

    if (EPI == EPI_EXP) {
        float rs[4][2];
#pragma unroll
        for (int mt = 0; mt < 4; mt++) { rs[mt][0] = 0.f; rs[mt][1] = 0.f; }
#pragma unroll
        for (int mt = 0; mt < 4; mt++)
#pragma unroll
            for (int nt = 0; nt < 8; nt++) {
                const float* a4 = acc[mt][nt];
                const int r   = m0 + wr * 64 + mt * 16 + (lane >> 2);
                const int col = n0 + wc * 64 + nt * 8 + (lane & 3) * 2;
                float p0 = exp2f(a4[0] * scale), p1 = exp2f(a4[1] * scale);
                float p2 = exp2f(a4[2] * scale), p3 = exp2f(a4[3] * scale);
                *(__half2*)(Ch + (size_t)r * Ntot + col)       = __floats2half2_rn(p0, p1);
                *(__half2*)(Ch + (size_t)(r + 8) * Ntot + col) = __floats2half2_rn(p2, p3);
                rs[mt][0] += p0 + p1;
                rs[mt][1] += p2 + p3;
            }
#pragma unroll
        for (int mt = 0; mt < 4; mt++)
#pragma unroll
            for (int h = 0; h < 2; h++) {
                float v = rs[mt][h];
                v += __shfl_xor_sync(0xffffffffu, v, 1);
                v += __shfl_xor_sync(0xffffffffu, v, 2);
                if ((lane & 3) == 0) {
                    const int r = m0 + wr * 64 + mt * 16 + (lane >> 2) + h * 8;
                    atomicAdd(rsum + r, v);
                }
            }
    } else {
#pragma unroll
        for (int mt = 0; mt < 4; mt++) {
            const int r = m0 + wr * 64 + mt * 16 + (lane >> 2);
            float i0 = 1.f, i1 = 1.f;
            if (EPI == EPI_NORM) { i0 = 1.f / rsum[r]; i1 = 1.f / rsum[r + 8]; }
#pragma unroll
            for (int nt = 0; nt < 8; nt++) {
                const float* a4 = acc[mt][nt];
                const int col = n0 + wc * 64 + nt * 8 + (lane & 3) * 2;
                if (EPI == EPI_F16) {
                    *(__half2*)(Ch + (size_t)r * Ntot + col)       = __floats2half2_rn(a4[0], a4[1]);
                    *(__half2*)(Ch + (size_t)(r + 8) * Ntot + col) = __floats2half2_rn(a4[2], a4[3]);
                } else {
                    *(float2*)(Cf + (size_t)r * Ntot + col)       = make_float2(a4[0] * i0, a4[1] * i0);
                    *(float2*)(Cf + (size_t)(r + 8) * Ntot + col) = make_float2(a4[2] * i1, a4[3] * i1);
                }
            }
        }
    }
}

// ---------------------------------------------------------------------------
// prep: fp32->fp16 for x,Wq,Wk,Wv (MLP=4: 4 independent float4 per thread);
// zeroes rsum and flags. ONE launch.
#define NX4 (BB * TT * DD / 4)      // 2,097,152
#define NW4 (DD * DD / 4)           //   262,144
#define NTOT4 (NX4 + 3 * NW4)       // 2,883,584
#define PSTRIDE (NTOT4 / 4)         //   720,896
__global__ __launch_bounds__(256) void prep_kernel(const float* __restrict__ x,
                                                   const float* __restrict__ Wq,
                                                   const float* __restrict__ Wk,
                                                   const float* __restrict__ Wv)
{
    const int i = blockIdx.x * 256 + threadIdx.x;
    if (i < BB * TT) g_rsum[i] = 0.f;
    if (i < 256) g_cnt[i] = 0;
#pragma unroll
    for (int k = 0; k < 4; k++) {
        int j = i + k * PSTRIDE;
        const float* src;
        __half* dst;
        if (j < NX4)                 { src = x;  dst = g_x16; }
        else if ((j -= NX4) < NW4)   { src = Wq; dst = g_w16; }
        else if ((j -= NW4) < NW4)   { src = Wk; dst = g_w16 + (size_t)DD * DD; }
        else                         { j -= NW4; src = Wv; dst = g_w16 + 2 * (size_t)DD * DD; }
        float4 v = ((const float4*)src)[j];
        __half2 h0 = __floats2half2_rn(v.x, v.y);
        __half2 h1 = __floats2half2_rn(v.z, v.w);
        uint2 o;
        o.x = *reinterpret_cast<uint32_t*>(&h0);
        o.y = *reinterpret_cast<uint32_t*>(&h1);
        ((uint2*)dst)[j] = o;
    }
}

// ---------------------------------------------------------------------------
// Fused attention, phases by block id (producers strictly first):
//   [0,1024):   Q/K projection
//   [1024,1536): V projection (fills QK tail; V[b] done before out(b) arrives)
//   [1536,3072): per batch b: 256 scores CTAs then 128 out CTAs (interleaved
//                across batches so out(b) co-runs with scores(b+1..))
// ---------------------------------------------------------------------------
#define SCALE2 (0.03125f * 1.44269504088896f)   // 1/sqrt(1024) * log2(e)

__global__ __launch_bounds__(128, 2) void fused_kernel(float* __restrict__ out)
{
    const int bid = blockIdx.x;
    if (bid < 1024) {
        const int z  = bid >> 9;                 // 0->Q, 1->K
        const int r  = bid & 511;
        const int n0 = (r & 7) * 128;
        const int rb = r >> 3;                   // global rowblock 0..63
        __half* C = z ? g_k16 : g_q16;
        gemm_f16<true, EPI_F16>(g_x16, g_w16 + (size_t)z * DD * DD,
                                nullptr, C, nullptr, DD, DD, 1.0f, rb * 128, n0);
        signal_cnt(&g_cnt[z * 64 + rb]);                  // target 8
    } else if (bid < 1536) {
        const int id = bid - 1024;
        const int n0 = (id & 7) * 128;
        const int rb = id >> 3;
        gemm_f16<true, EPI_F16>(g_x16, g_w16 + 2 * (size_t)DD * DD,
                                nullptr, g_v16, nullptr, DD, DD, 1.0f, rb * 128, n0);
        signal_cnt(&g_cnt[192 + (rb >> 4)]);              // target 128 per batch
    } else {
        const int id = bid - 1536;
        const int b  = id / 384;
        const int r  = id - b * 384;
        if (r < 256) {
            const int qb = r >> 4;
            const int kb = r & 15;
            wait_cnt(&g_cnt[b * 16 + qb], 8);             // Q rows ready
            wait_cnt(&g_cnt[64 + b * 16 + kb], 8);        // K rows ready
            gemm_f16<true, EPI_EXP>(g_q16 + (size_t)b * TT * DD,
                                    g_k16 + (size_t)b * TT * DD,
                                    nullptr, g_p16 + (size_t)b * TT * TT,
                                    g_rsum + (size_t)b * TT,
                                    TT, DD, SCALE2, qb * 128, kb * 128);
            signal_cnt(&g_cnt[128 + b * 16 + qb]);        // target 16
        } else {
            const int o  = r - 256;
            const int qb = o >> 3;
            const int n0 = (o & 7) * 128;
            wait_cnt(&g_cnt[128 + b * 16 + qb], 16);      // P rows + rsum ready
            wait_cnt(&g_cnt[192 + b], 128);               // V[b] ready
            gemm_f16<false, EPI_NORM>(g_p16 + (size_t)b * TT * TT,
                                      g_v16 + (size_t)b * TT * DD,
                                      out + (size_t)b * TT * DD, nullptr,
                                      g_rsum + (size_t)b * TT,
                                      DD, TT, 1.0f, qb * 128, n0);
        }
    }
}

// ---------------------------------------------------------------------------
extern "C" void kernel_launch(void* const* d_in, const int* in_sizes, int n_in,
                              void* d_out, int out_size)
{
    (void)in_sizes; (void)n_in; (void)out_size;
    const float* x  = (const float*)d_in[0];
    const float* Wq = (const float*)d_in[1];
    const float* Wk = (const float*)d_in[2];
    const float* Wv = (const float*)d_in[3];
    float* out = (float*)d_out;

    cudaFuncSetAttribute(fused_kernel, cudaFuncAttributeMaxDynamicSharedMemorySize, SMEM_BYTES);

    prep_kernel<<<(PSTRIDE + 255) / 256, 256>>>(x, Wq, Wk, Wv);   // grid 2816

    fused_kernel<<<3072, 128, SMEM_BYTES>>>(out);
}

// round 17
// speedup vs baseline: 1.0643x; 1.0643x over previous
#include <cuda_runtime.h>
#include <cuda_fp16.h>
#include <stdint.h>
#include <math_constants.h>

#define BB 4
#define TT 2048
#define DD 1024
#define KCH 64

// ---- scratch (allocation-free rule: __device__ globals) ----
__device__ __align__(256) __half g_x16[(size_t)BB * TT * DD];
__device__ __align__(256) __half g_w16[3 * (size_t)DD * DD];     // Wq,Wk,Wv
__device__ __align__(256) __half g_q16[(size_t)BB * TT * DD];
__device__ __align__(256) __half g_k16[(size_t)BB * TT * DD];
__device__ __align__(256) __half g_v16[(size_t)BB * TT * DD];
__device__ __align__(256) __half g_p16[(size_t)BB * TT * TT];    // unnormalized exp(s), fp16
__device__ __align__(256) float  g_rsum[(size_t)BB * TT];        // per-row sum of exp(s)
__device__ int g_cnt[256];   // [0..127] Q/K rowblocks, [128..191] scores rowblocks, [192..195] V per batch

// SMEM: 3 stages x (A 16K | B 16K)
#define STAGE 32768
#define NSTAGE 3
#define SMEM_BYTES (NSTAGE * STAGE)   // 98304

__device__ __forceinline__ uint32_t smem_u32(const void* p) {
    uint32_t a;
    asm("{ .reg .u64 t; cvta.to.shared.u64 t, %1; cvt.u32.u64 %0, t; }" : "=r"(a) : "l"(p));
    return a;
}
__device__ __forceinline__ void cpa16(uint32_t dst, const void* src) {
    asm volatile("cp.async.cg.shared.global [%0], [%1], 16;" :: "r"(dst), "l"(src));
}
__device__ __forceinline__ void cpa_commit() { asm volatile("cp.async.commit_group;" ::: "memory"); }
__device__ __forceinline__ void cpa_wait1()  { asm volatile("cp.async.wait_group 1;" ::: "memory"); }

__device__ __forceinline__ void ldsm4(uint32_t addr, uint32_t r[4]) {
    asm volatile("ldmatrix.sync.aligned.m8n8.x4.shared.b16 {%0,%1,%2,%3}, [%4];"
                 : "=r"(r[0]), "=r"(r[1]), "=r"(r[2]), "=r"(r[3]) : "r"(addr));
}
__device__ __forceinline__ void ldsm4t(uint32_t addr, uint32_t r[4]) {
    asm volatile("ldmatrix.sync.aligned.m8n8.x4.trans.shared.b16 {%0,%1,%2,%3}, [%4];"
                 : "=r"(r[0]), "=r"(r[1]), "=r"(r[2]), "=r"(r[3]) : "r"(addr));
}
__device__ __forceinline__ void mma_f16(float c[4], const uint32_t a[4],
                                        uint32_t b0, uint32_t b1) {
    asm volatile("mma.sync.aligned.m16n8k16.row.col.f32.f16.f16.f32 "
                 "{%0,%1,%2,%3}, {%4,%5,%6,%7}, {%8,%9}, {%0,%1,%2,%3};"
                 : "+f"(c[0]), "+f"(c[1]), "+f"(c[2]), "+f"(c[3])
                 : "r"(a[0]), "r"(a[1]), "r"(a[2]), "r"(a[3]), "r"(b0), "r"(b1));
}

// producer/consumer flags (block-id monotone order guarantees progress)
__device__ __forceinline__ void signal_cnt(int* c) {
    __threadfence();
    __syncthreads();
    if (threadIdx.x == 0) atomicAdd(c, 1);
}
__device__ __forceinline__ void wait_cnt(const int* c, int target) {
    if (threadIdx.x == 0) {
        int v;
        do {
            asm volatile("ld.global.acquire.gpu.b32 %0, [%1];" : "=r"(v) : "l"(c));
        } while (v < target);
    }
    __syncthreads();
}

// Epilogue modes
#define EPI_F16   0
#define EPI_EXP   1
#define EPI_NORM  2

// ---------------------------------------------------------------------------
// 1-pass fp16 HMMA GEMM (R11/R13 core): C[m,n] = sum_k A[m,k]*B'[k,n]
// ---------------------------------------------------------------------------
template <bool BT, int EPI>
__device__ __forceinline__ void gemm_f16(const __half* __restrict__ A,
                                         const __half* __restrict__ Bm,
                                         float* Cf, __half* Ch,
                                         float* rsum,
                                         int Ntot, int K, float scale,
                                         int m0, int n0)
{
    extern __shared__ char smc[];
    const uint32_t sb  = smem_u32(smc);
    const int tid  = threadIdx.x;
    const int lane = tid & 31;
    const int wid  = tid >> 5;
    const int wr   = wid >> 1;
    const int wc   = wid & 1;

    float acc[4][8][4];
#pragma unroll
    for (int i = 0; i < 4; i++)
#pragma unroll
        for (int j = 0; j < 8; j++)
#pragma unroll
            for (int e = 0; e < 4; e++) acc[i][j][e] = 0.f;

    const int nch = K / KCH;

    auto stage = [&](int c, int s) {
        const uint32_t base = sb + s * STAGE;
        const int k0 = c * KCH;
#pragma unroll
        for (int i = 0; i < 8; i++) {
            int u = tid + i * 128;
            int row = u >> 3, ch = u & 7;
            uint32_t off = (uint32_t)(row * 128 + ((ch * 16) ^ ((row & 7) * 16)));
            cpa16(base + off, A + (size_t)(m0 + row) * K + k0 + ch * 8);
        }
        if (BT) {
#pragma unroll
            for (int i = 0; i < 8; i++) {
                int u = tid + i * 128;
                int row = u >> 3, ch = u & 7;
                uint32_t off = (uint32_t)(row * 128 + ((ch * 16) ^ ((row & 7) * 16)));
                cpa16(base + 16384 + off, Bm + (size_t)(n0 + row) * K + k0 + ch * 8);
            }
        } else {
#pragma unroll
            for (int i = 0; i < 8; i++) {
                int u = tid + i * 128;
                int kr = u >> 4, ch = u & 15;
                uint32_t off = (uint32_t)(kr * 256 + ((ch * 16) ^ ((kr & 7) * 16)));
                cpa16(base + 16384 + off, Bm + (size_t)(k0 + kr) * Ntot + n0 + ch * 8);
            }
        }
        cpa_commit();
    };

    auto load_a = [&](uint32_t base, int ks, uint32_t Af[4][4]) {
        const int arow = lane & 15;
        const uint32_t ach = (uint32_t)(((ks * 2 + (lane >> 4)) * 16) ^ ((lane & 7) * 16));
#pragma unroll
        for (int mt = 0; mt < 4; mt++) {
            const uint32_t aoff = (uint32_t)((wr * 64 + mt * 16 + arow) * 128) + ach;
            ldsm4(base + aoff, Af[mt]);
        }
    };
    auto load_b = [&](uint32_t base, int ks, uint32_t Bf[4][4]) {
        if (BT) {
            const int brow = (lane >> 4) * 8 + (lane & 7);
            const uint32_t bch =
                (uint32_t)(((ks * 2 + ((lane >> 3) & 1)) * 16) ^ ((lane & 7) * 16));
#pragma unroll
            for (int ng = 0; ng < 4; ng++) {
                const uint32_t boff = (uint32_t)((wc * 64 + ng * 16 + brow) * 128) + bch;
                ldsm4(base + 16384 + boff, Bf[ng]);
            }
        } else {
            const int krow = ks * 16 + (lane & 15);
#pragma unroll
            for (int ng = 0; ng < 4; ng++) {
                const uint32_t chunk =
                    (uint32_t)(wc * 8 + ng * 2 + (lane >> 4)) ^ (uint32_t)(lane & 7);
                ldsm4t(base + 16384 + (uint32_t)(krow * 256) + chunk * 16, Bf[ng]);
            }
        }
    };

    auto compute = [&](int s) {
        const uint32_t base = sb + s * STAGE;
        uint32_t Af[2][4][4], Bf[2][4][4];
        load_a(base, 0, Af[0]);
        load_b(base, 0, Bf[0]);
#pragma unroll
        for (int ks = 0; ks < KCH / 16; ks++) {
            const int cur = ks & 1;
            if (ks + 1 < KCH / 16) {
                load_a(base, ks + 1, Af[cur ^ 1]);
                load_b(base, ks + 1, Bf[cur ^ 1]);
            }
#pragma unroll
            for (int mt = 0; mt < 4; mt++)
#pragma unroll
                for (int ng = 0; ng < 4; ng++) {
                    mma_f16(acc[mt][ng * 2],     Af[cur][mt], Bf[cur][ng][0], Bf[cur][ng][1]);
                    mma_f16(acc[mt][ng * 2 + 1], Af[cur][mt], Bf[cur][ng][2], Bf[cur][ng][3]);
                }
        }
    };

    stage(0, 0);
    if (nch > 1) stage(1, 1);
    for (int c = 0; c < nch; c++) {
        cpa_wait1();
        __syncthreads();
        if (c + 2 < nch) stage(c + 2, (c + 2) % NSTAGE);
        compute(c % NSTAGE);
    }

    if (EPI == EPI_EXP) {
        float rs[4][2];
#pragma unroll
        for (int mt = 0; mt < 4; mt++) { rs[mt][0] = 0.f; rs[mt][1] = 0.f; }
#pragma unroll
        for (int mt = 0; mt < 4; mt++)
#pragma unroll
            for (int nt = 0; nt < 8; nt++) {
                const float* a4 = acc[mt][nt];
                const int r   = m0 + wr * 64 + mt * 16 + (lane >> 2);
                const int col = n0 + wc * 64 + nt * 8 + (lane & 3) * 2;
                float p0 = exp2f(a4[0] * scale), p1 = exp2f(a4[1] * scale);
                float p2 = exp2f(a4[2] * scale), p3 = exp2f(a4[3] * scale);
                *(__half2*)(Ch + (size_t)r * Ntot + col)       = __floats2half2_rn(p0, p1);
                *(__half2*)(Ch + (size_t)(r + 8) * Ntot + col) = __floats2half2_rn(p2, p3);
                rs[mt][0] += p0 + p1;
                rs[mt][1] += p2 + p3;
            }
#pragma unroll
        for (int mt = 0; mt < 4; mt++)
#pragma unroll
            for (int h = 0; h < 2; h++) {
                float v = rs[mt][h];
                v += __shfl_xor_sync(0xffffffffu, v, 1);
                v += __shfl_xor_sync(0xffffffffu, v, 2);
                if ((lane & 3) == 0) {
                    const int r = m0 + wr * 64 + mt * 16 + (lane >> 2) + h * 8;
                    atomicAdd(rsum + r, v);
                }
            }
    } else {
#pragma unroll
        for (int mt = 0; mt < 4; mt++) {
            const int r = m0 + wr * 64 + mt * 16 + (lane >> 2);
            float i0 = 1.f, i1 = 1.f;
            if (EPI == EPI_NORM) { i0 = 1.f / rsum[r]; i1 = 1.f / rsum[r + 8]; }
#pragma unroll
            for (int nt = 0; nt < 8; nt++) {
                const float* a4 = acc[mt][nt];
                const int col = n0 + wc * 64 + nt * 8 + (lane & 3) * 2;
                if (EPI == EPI_F16) {
                    *(__half2*)(Ch + (size_t)r * Ntot + col)       = __floats2half2_rn(a4[0], a4[1]);
                    *(__half2*)(Ch + (size_t)(r + 8) * Ntot + col) = __floats2half2_rn(a4[2], a4[3]);
                } else {
                    *(float2*)(Cf + (size_t)r * Ntot + col)       = make_float2(a4[0] * i0, a4[1] * i0);
                    *(float2*)(Cf + (size_t)(r + 8) * Ntot + col) = make_float2(a4[2] * i1, a4[3] * i1);
                }
            }
        }
    }
}

// ---------------------------------------------------------------------------
// prep: fp32 -> fp16 for x,Wq,Wk,Wv; zeroes rsum and flags. ONE launch (R13).
#define NX4 (BB * TT * DD / 4)
#define NW4 (DD * DD / 4)
__global__ __launch_bounds__(256) void prep_kernel(const float* __restrict__ x,
                                                   const float* __restrict__ Wq,
                                                   const float* __restrict__ Wk,
                                                   const float* __restrict__ Wv)
{
    int i = blockIdx.x * 256 + threadIdx.x;
    if (i < BB * TT) g_rsum[i] = 0.f;
    if (i < 256) g_cnt[i] = 0;
    const float* src;
    __half* dst;
    int j = i;
    if (j < NX4)                 { src = x;  dst = g_x16; }
    else if ((j -= NX4) < NW4)   { src = Wq; dst = g_w16; }
    else if ((j -= NW4) < NW4)   { src = Wk; dst = g_w16 + (size_t)DD * DD; }
    else if ((j -= NW4) < NW4)   { src = Wv; dst = g_w16 + 2 * (size_t)DD * DD; }
    else return;
    float4 v = ((const float4*)src)[j];
    __half2 h0 = __floats2half2_rn(v.x, v.y);
    __half2 h1 = __floats2half2_rn(v.z, v.w);
    uint2 o;
    o.x = *reinterpret_cast<uint32_t*>(&h0);
    o.y = *reinterpret_cast<uint32_t*>(&h1);
    ((uint2*)dst)[j] = o;
}

// ---------------------------------------------------------------------------
// Fused attention (R13 phase order), QK phase z-INTERLEAVED so each batch's
// Q and K complete together early:
//   [0,1024):    Q/K projection — rb-major, z fastest (ids 0..255 = batch 0 Q+K)
//   [1024,2048): scores + exp   (waits Q,K rowblocks)
//   [2048,2560): V projection
//   [2560,3072): out = P*V / rsum
// ---------------------------------------------------------------------------
#define SCALE2 (0.03125f * 1.44269504088896f)   // 1/sqrt(1024) * log2(e)

__global__ __launch_bounds__(128, 2) void fused_kernel(float* __restrict__ out)
{
    const int bid = blockIdx.x;
    if (bid < 1024) {
        const int rb = bid >> 4;                 // global rowblock 0..63 (b = rb>>4)
        const int z  = (bid >> 3) & 1;           // Q/K interleaved per rowblock
        const int n0 = (bid & 7) * 128;
        __half* C = z ? g_k16 : g_q16;
        gemm_f16<true, EPI_F16>(g_x16, g_w16 + (size_t)z * DD * DD,
                                nullptr, C, nullptr, DD, DD, 1.0f, rb * 128, n0);
        signal_cnt(&g_cnt[z * 64 + rb]);                  // target 8
    } else if (bid < 2048) {
        const int id = bid - 1024;
        const int b  = id >> 8;
        const int qb = (id >> 4) & 15;
        const int kb = id & 15;
        wait_cnt(&g_cnt[b * 16 + qb], 8);                 // Q rows ready
        wait_cnt(&g_cnt[64 + b * 16 + kb], 8);            // K rows ready
        gemm_f16<true, EPI_EXP>(g_q16 + (size_t)b * TT * DD,
                                g_k16 + (size_t)b * TT * DD,
                                nullptr, g_p16 + (size_t)b * TT * TT,
                                g_rsum + (size_t)b * TT,
                                TT, DD, SCALE2, qb * 128, kb * 128);
        signal_cnt(&g_cnt[128 + b * 16 + qb]);            // target 16
    } else if (bid < 2560) {
        const int id = bid - 2048;
        const int n0 = (id & 7) * 128;
        const int rb = id >> 3;
        gemm_f16<true, EPI_F16>(g_x16, g_w16 + 2 * (size_t)DD * DD,
                                nullptr, g_v16, nullptr, DD, DD, 1.0f, rb * 128, n0);
        signal_cnt(&g_cnt[192 + (rb >> 4)]);              // target 128 per batch
    } else {
        const int id = bid - 2560;
        const int b  = id >> 7;
        const int qb = (id >> 3) & 15;
        const int n0 = (id & 7) * 128;
        wait_cnt(&g_cnt[128 + b * 16 + qb], 16);          // P rows + rsum ready
        wait_cnt(&g_cnt[192 + b], 128);                   // V[b] ready
        gemm_f16<false, EPI_NORM>(g_p16 + (size_t)b * TT * TT,
                                  g_v16 + (size_t)b * TT * DD,
                                  out + (size_t)b * TT * DD, nullptr,
                                  g_rsum + (size_t)b * TT,
                                  DD, TT, 1.0f, qb * 128, n0);
    }
}

// ---------------------------------------------------------------------------
extern "C" void kernel_launch(void* const* d_in, const int* in_sizes, int n_in,
                              void* d_out, int out_size)
{
    (void)in_sizes; (void)n_in; (void)out_size;
    const float* x  = (const float*)d_in[0];
    const float* Wq = (const float*)d_in[1];
    const float* Wk = (const float*)d_in[2];
    const float* Wv = (const float*)d_in[3];
    float* out = (float*)d_out;

    cudaFuncSetAttribute(fused_kernel, cudaFuncAttributeMaxDynamicSharedMemorySize, SMEM_BYTES);

    const int ntot = NX4 + 3 * NW4;
    prep_kernel<<<(ntot + 255) / 256, 256>>>(x, Wq, Wk, Wv);

    fused_kernel<<<3072, 128, SMEM_BYTES>>>(out);
}